// round 4
// baseline (speedup 1.0000x reference)
#include <cuda_runtime.h>

// CharRNN: B=512, T=2048, VOCAB=96, EMBED=32, HIDDEN=128
// R3: balanced crossbar/fma/issue design.
//  - cell  : 256 thr = 64 j-pairs x 4 k-slices. Weights DUPLICATED in regs
//            ((w,w) u64). Per k: 2 LDS.64 (row-paired h) + 4 FFMA2.
//  - dec   : 96 thr = 24 v-quads x 4 k-slices. h read from a DUPLICATED smem
//            copy ((h,h) u64, written by cell epilogue). Per k: 4 LDS.64 +
//            8 FFMA2 with naturally paired weights (w_v0,w_v1).
//  - k-slice partials merged via 2-level shfl.xor; tanh via ex2/rcp approx.
//  - one __syncthreads per step; decoder lags cell by one step.

#define VOCABN 96
#define EMBEDN 32
#define HID    128
#define BATCH  512
#define TLEN   2048
#define BROWS  4
#define NBLK   (BATCH / BROWS)   // 128
#define NTHR   352               // 8 cell warps + 3 decoder warps
#define WCS    (EMBEDN + HID)    // 160

typedef unsigned long long u64;

__device__ __forceinline__ u64 ffma2(u64 a, u64 b, u64 c) {
    u64 d;
    asm("fma.rn.f32x2 %0, %1, %2, %3;" : "=l"(d) : "l"(a), "l"(b), "l"(c));
    return d;
}
__device__ __forceinline__ u64 fadd2(u64 a, u64 b) {
    u64 d;
    asm("add.rn.f32x2 %0, %1, %2;" : "=l"(d) : "l"(a), "l"(b));
    return d;
}
__device__ __forceinline__ u64 pack2(float x, float y) {
    u64 d;
    asm("mov.b64 %0, {%1, %2};" : "=l"(d) : "f"(x), "f"(y));
    return d;
}
__device__ __forceinline__ float2 unpack2(u64 a) {
    float2 r;
    asm("mov.b64 {%0, %1}, %2;" : "=f"(r.x), "=f"(r.y) : "l"(a));
    return r;
}
__device__ __forceinline__ u64 shflx64(u64 v, int m) {
    float2 p = unpack2(v);
    p.x = __shfl_xor_sync(0xffffffffu, p.x, m);
    p.y = __shfl_xor_sync(0xffffffffu, p.y, m);
    return pack2(p.x, p.y);
}
// tanh(x) = 1 - 2/(exp(2x)+1), via HW ex2/rcp approx (~1e-7 rel err)
__device__ __forceinline__ float tanh_fast(float x) {
    float e;
    asm("ex2.approx.f32 %0, %1;" : "=f"(e) : "f"(x * 2.8853900817779268f));
    float r;
    asm("rcp.approx.f32 %0, %1;" : "=f"(r) : "f"(e + 1.0f));
    return fmaf(-2.0f, r, 1.0f);
}

// SMEM (floats):
//  Et : 96*128 = 12288                [v*128 + j]   e@We^T + b_cell
//  hp : 2 buf * 2 rp * 128 float2     row-paired h: (r0,r1) / (r2,r3)
//  hd : 2 buf * 4 r  * 128 u64        duplicated h: (h,h)
//  xs : 2048*4 ints                   [t*4 + r]
#define F_ET 0
#define F_HP (F_ET + VOCABN*HID)          // 12288
#define F_HD (F_HP + 2*2*HID*2)           // 13312
#define F_XS (F_HD + 2*4*HID*2)           // 15360
#define SMEM_FLOATS (F_XS + BROWS*TLEN)   // 23552
#define SMEM_BYTES  (SMEM_FLOATS * 4)     // 94208

__global__ void __launch_bounds__(NTHR, 1)
charrnn_kernel(const int* __restrict__ x,
               const float* __restrict__ h0,
               const float* __restrict__ emb,
               const float* __restrict__ Wcell,   // [128][160]
               const float* __restrict__ bcell,   // [128]
               const float* __restrict__ Wdec,    // [96][128]
               const float* __restrict__ bdec,    // [96]
               float* __restrict__ out,           // [512][2048][96]
               float* __restrict__ hfin)          // [512][128] or null
{
    extern __shared__ float smem[];
    float*  Et = smem + F_ET;
    float2* hp = (float2*)(smem + F_HP);
    u64*    hd = (u64*)(smem + F_HD);
    int*    xs = (int*)(smem + F_XS);

    const int tid = threadIdx.x;
    const int b0  = blockIdx.x * BROWS;
    const bool isCell = (tid < 256);
    const size_t RS = (size_t)TLEN * VOCABN;

    // role indices
    const int up = tid >> 2;          // cell: j-pair 0..63
    const int s  = tid & 3;           // k-slice 0..3 (also = batch row for epilogue)
    const int ks = s * 32;
    const int j0 = 2 * up;            // cell only (valid when isCell)
    const int dq = (tid - 256) >> 2;  // dec: v-quad 0..23
    const int v0 = 4 * dq;

    // ---------------- per-thread weight registers ----------------
    u64 wd0[32], wd1[32];   // cell: duplicated (w,w) for j0, j1
    u64 w2a[32], w2b[32];   // dec: (w_v0,w_v1), (w_v2,w_v3)
    u64 bda = 0, bdb = 0;

    if (isCell) {
        const float* r0p = Wcell + j0 * WCS + EMBEDN + ks;
        const float* r1p = r0p + WCS;
        #pragma unroll
        for (int k = 0; k < 32; k++) {
            float a = r0p[k], b = r1p[k];
            wd0[k] = pack2(a, a);
            wd1[k] = pack2(b, b);
        }
    } else {
        const float* dp = Wdec + v0 * HID + ks;
        #pragma unroll
        for (int k = 0; k < 32; k++) {
            w2a[k] = pack2(dp[k], dp[HID + k]);
            w2b[k] = pack2(dp[2 * HID + k], dp[3 * HID + k]);
        }
        bda = pack2(bdec[v0], bdec[v0 + 1]);
        bdb = pack2(bdec[v0 + 2], bdec[v0 + 3]);
    }

    // ---------------- Et table (threads 0..127, j = tid) ----------------
    if (tid < HID) {
        const int j = tid;
        float we[EMBEDN];
        #pragma unroll
        for (int k = 0; k < EMBEDN; k++)
            we[k] = Wcell[j * WCS + k];
        const float bc = bcell[j];
        for (int vv = 0; vv < VOCABN; vv++) {
            float a = bc;
            #pragma unroll
            for (int k = 0; k < EMBEDN; k++)
                a = fmaf(emb[vv * EMBEDN + k], we[k], a);
            Et[vv * HID + j] = a;
        }
    }

    // ---------------- token prefetch ----------------
    for (int i = tid; i < BROWS * TLEN; i += NTHR) {
        int t = i >> 2, r = i & 3;
        xs[i] = x[(b0 + r) * TLEN + t];
    }

    // ---------------- initial h into buffer 0 ----------------
    if (isCell) {
        float a = h0[(b0 + s) * HID + j0];
        float b = h0[(b0 + s) * HID + j0 + 1];
        float* hpf = (float*)(hp + (s >> 1) * HID);     // buf 0, row-pair s>>1
        hpf[j0 * 2 + (s & 1)]       = a;
        hpf[(j0 + 1) * 2 + (s & 1)] = b;
        u64* hdp = hd + s * HID;                        // buf 0, row s
        hdp[j0]     = pack2(a, a);
        hdp[j0 + 1] = pack2(b, b);
    }
    __syncthreads();

    float th0 = 0.f, th1 = 0.f;   // cell: last h values for (j0,j0+1), row s

    // ---------------- main recurrence ----------------
    #pragma unroll 1
    for (int t = 0; t <= TLEN; t++) {
        if (isCell) {
            if (t < TLEN) {
                const u64* h01p = (const u64*)(hp + (t & 1) * (2 * HID)) + ks;
                const u64* h23p = h01p + HID;
                u64 a00 = 0, a01v = 0, a10 = 0, a11 = 0;
                #pragma unroll
                for (int k = 0; k < 32; k++) {
                    u64 h01v = h01p[k];
                    u64 h23v = h23p[k];
                    a00  = ffma2(h01v, wd0[k], a00);
                    a01v = ffma2(h23v, wd0[k], a01v);
                    a10  = ffma2(h01v, wd1[k], a10);
                    a11  = ffma2(h23v, wd1[k], a11);
                }
                // merge 4 k-slices (lanes up*4+s, xor 1 then 2)
                a00  = fadd2(a00,  shflx64(a00, 1));
                a01v = fadd2(a01v, shflx64(a01v, 1));
                a10  = fadd2(a10,  shflx64(a10, 1));
                a11  = fadd2(a11,  shflx64(a11, 1));
                a00  = fadd2(a00,  shflx64(a00, 2));
                a01v = fadd2(a01v, shflx64(a01v, 2));
                a10  = fadd2(a10,  shflx64(a10, 2));
                a11  = fadd2(a11,  shflx64(a11, 2));
                // lane s finalizes batch row s
                u64 abj0 = (s & 2) ? a01v : a00;
                u64 abj1 = (s & 2) ? a11  : a10;
                float2 pj0 = unpack2(abj0), pj1 = unpack2(abj1);
                float uj0 = (s & 1) ? pj0.y : pj0.x;
                float uj1 = (s & 1) ? pj1.y : pj1.x;
                const int xv = xs[t * 4 + s];
                const float2 et2 = *(const float2*)&Et[xv * HID + j0];
                uj0 += et2.x;
                uj1 += et2.y;
                th0 = tanh_fast(uj0);
                th1 = tanh_fast(uj1);
                const int nb = (t + 1) & 1;
                float* hpf = (float*)(hp + nb * (2 * HID) + (s >> 1) * HID);
                hpf[j0 * 2 + (s & 1)]       = th0;
                hpf[(j0 + 1) * 2 + (s & 1)] = th1;
                u64* hdp = hd + nb * (4 * HID) + s * HID;
                hdp[j0]     = pack2(th0, th0);
                hdp[j0 + 1] = pack2(th1, th1);
            }
        } else if (t > 0) {
            // decoder: out[t-1] from h_t (hd buf t&1)
            const u64* hb = hd + (t & 1) * (4 * HID) + ks;
            u64 A0 = 0, A1 = 0, A2 = 0, A3 = 0;
            u64 B0 = 0, B1 = 0, B2 = 0, B3 = 0;
            #pragma unroll
            for (int k = 0; k < 32; k++) {
                u64 d0 = hb[k];
                u64 d1 = hb[HID + k];
                u64 d2 = hb[2 * HID + k];
                u64 d3 = hb[3 * HID + k];
                A0 = ffma2(d0, w2a[k], A0);  B0 = ffma2(d0, w2b[k], B0);
                A1 = ffma2(d1, w2a[k], A1);  B1 = ffma2(d1, w2b[k], B1);
                A2 = ffma2(d2, w2a[k], A2);  B2 = ffma2(d2, w2b[k], B2);
                A3 = ffma2(d3, w2a[k], A3);  B3 = ffma2(d3, w2b[k], B3);
            }
            A0 = fadd2(A0, shflx64(A0, 1));  B0 = fadd2(B0, shflx64(B0, 1));
            A1 = fadd2(A1, shflx64(A1, 1));  B1 = fadd2(B1, shflx64(B1, 1));
            A2 = fadd2(A2, shflx64(A2, 1));  B2 = fadd2(B2, shflx64(B2, 1));
            A3 = fadd2(A3, shflx64(A3, 1));  B3 = fadd2(B3, shflx64(B3, 1));
            A0 = fadd2(A0, shflx64(A0, 2));  B0 = fadd2(B0, shflx64(B0, 2));
            A1 = fadd2(A1, shflx64(A1, 2));  B1 = fadd2(B1, shflx64(B1, 2));
            A2 = fadd2(A2, shflx64(A2, 2));  B2 = fadd2(B2, shflx64(B2, 2));
            A3 = fadd2(A3, shflx64(A3, 2));  B3 = fadd2(B3, shflx64(B3, 2));
            // lane s -> batch row s
            u64 selA = (s & 2) ? ((s & 1) ? A3 : A2) : ((s & 1) ? A1 : A0);
            u64 selB = (s & 2) ? ((s & 1) ? B3 : B2) : ((s & 1) ? B1 : B0);
            selA = fadd2(selA, bda);
            selB = fadd2(selB, bdb);
            float2 ra = unpack2(selA), rb = unpack2(selB);
            float4 o4 = make_float4(ra.x, ra.y, rb.x, rb.y);
            *(float4*)&out[(size_t)(b0 + s) * RS + (size_t)(t - 1) * VOCABN + v0] = o4;
        }
        __syncthreads();
    }

    // ---------------- final hidden state ----------------
    if (isCell && hfin) {
        *(float2*)&hfin[(b0 + s) * HID + j0] = make_float2(th0, th1);
    }
}

extern "C" void kernel_launch(void* const* d_in, const int* in_sizes, int n_in,
                              void* d_out, int out_size)
{
    const int*   x     = (const int*)d_in[0];
    const float* h0    = (const float*)d_in[1];
    const float* emb   = (const float*)d_in[2];
    const float* Wcell = (const float*)d_in[3];
    const float* bcell = (const float*)d_in[4];
    const float* Wdec  = (const float*)d_in[5];
    const float* bdec  = (const float*)d_in[6];

    float* out = (float*)d_out;
    const long long outs_elems = (long long)BATCH * TLEN * VOCABN;
    float* hfin = nullptr;
    if ((long long)out_size >= outs_elems + (long long)BATCH * HID)
        hfin = out + outs_elems;

    cudaFuncSetAttribute(charrnn_kernel,
                         cudaFuncAttributeMaxDynamicSharedMemorySize, SMEM_BYTES);

    charrnn_kernel<<<NBLK, NTHR, SMEM_BYTES>>>(x, h0, emb, Wcell, bcell,
                                               Wdec, bdec, out, hfin);
}

// round 5
// speedup vs baseline: 2.3080x; 2.3080x over previous
#include <cuda_runtime.h>

// CharRNN: B=512, T=2048, VOCAB=96, EMBED=32, HIDDEN=128
// R4 = R3 architecture with bank-conflict-free padded h layout + cheaper
// shuffle reduction.
//  - cell  : 256 thr = 64 j-pairs x 4 k-slices. Duplicated (w,w) weights in
//            regs. Per k: 2 LDS.64 (row-paired h) + 4 FFMA2.
//  - dec   : 96 thr = 24 v-quads x 4 k-slices. Duplicated (h,h) smem copy.
//            Per k: 4 LDS.64 + 8 FFMA2 with (w_v0,w_v1)/(w_v2,w_v3) regs.
//  - h arrays padded: physical u64 index k -> k + (k>>5)  (slice base 33*s)
//    => the 4 k-slices hit distinct banks; all hot LDS.64 are 1 phase.
//  - reduce-scatter shuffles (send only what partner needs).
//  - one __syncthreads per step; decoder lags cell by one step.

#define VOCABN 96
#define EMBEDN 32
#define HID    128
#define BATCH  512
#define TLEN   2048
#define BROWS  4
#define NBLK   (BATCH / BROWS)   // 128
#define NTHR   352               // 8 cell warps + 3 decoder warps
#define WCS    (EMBEDN + HID)    // 160

// padded sizes (u64 units): 128 k -> 132 slots per row(-pair)
#define KPAD     132
#define HP_BUF   (2 * KPAD)      // u64 per hp buffer (2 row-pairs)
#define HD_BUF   (4 * KPAD)      // u64 per hd buffer (4 rows)

typedef unsigned long long u64;

__device__ __forceinline__ u64 ffma2(u64 a, u64 b, u64 c) {
    u64 d;
    asm("fma.rn.f32x2 %0, %1, %2, %3;" : "=l"(d) : "l"(a), "l"(b), "l"(c));
    return d;
}
__device__ __forceinline__ u64 fadd2(u64 a, u64 b) {
    u64 d;
    asm("add.rn.f32x2 %0, %1, %2;" : "=l"(d) : "l"(a), "l"(b));
    return d;
}
__device__ __forceinline__ u64 pack2(float x, float y) {
    u64 d;
    asm("mov.b64 %0, {%1, %2};" : "=l"(d) : "f"(x), "f"(y));
    return d;
}
__device__ __forceinline__ float2 unpack2(u64 a) {
    float2 r;
    asm("mov.b64 {%0, %1}, %2;" : "=f"(r.x), "=f"(r.y) : "l"(a));
    return r;
}
__device__ __forceinline__ u64 shflx64(u64 v, int m) {
    float2 p = unpack2(v);
    p.x = __shfl_xor_sync(0xffffffffu, p.x, m);
    p.y = __shfl_xor_sync(0xffffffffu, p.y, m);
    return pack2(p.x, p.y);
}
// tanh(x) = 1 - 2/(exp(2x)+1) via ex2/rcp approx (~1e-7 rel err)
__device__ __forceinline__ float tanh_fast(float x) {
    float e;
    asm("ex2.approx.f32 %0, %1;" : "=f"(e) : "f"(x * 2.8853900817779268f));
    float r;
    asm("rcp.approx.f32 %0, %1;" : "=f"(r) : "f"(e + 1.0f));
    return fmaf(-2.0f, r, 1.0f);
}

// SMEM (floats):
//  Et : 96*128 = 12288          [v*128 + j]
//  hp : 2 buf * HP_BUF u64      row-paired h (padded)
//  hd : 2 buf * HD_BUF u64      duplicated h (padded)
//  xs : 2048*4 ints
#define F_ET 0
#define F_HP (F_ET + VOCABN*HID)              // 12288 (16B aligned)
#define F_HD (F_HP + 2*HP_BUF*2)              // + 1056
#define F_XS (F_HD + 2*HD_BUF*2)              // + 2112
#define SMEM_FLOATS (F_XS + BROWS*TLEN)
#define SMEM_BYTES  (SMEM_FLOATS * 4)

__global__ void __launch_bounds__(NTHR, 1)
charrnn_kernel(const int* __restrict__ x,
               const float* __restrict__ h0,
               const float* __restrict__ emb,
               const float* __restrict__ Wcell,   // [128][160]
               const float* __restrict__ bcell,   // [128]
               const float* __restrict__ Wdec,    // [96][128]
               const float* __restrict__ bdec,    // [96]
               float* __restrict__ out,           // [512][2048][96]
               float* __restrict__ hfin)          // [512][128] or null
{
    extern __shared__ float smem[];
    float* Et  = smem + F_ET;
    u64*   hpU = (u64*)(smem + F_HP);
    u64*   hdU = (u64*)(smem + F_HD);
    int*   xs  = (int*)(smem + F_XS);

    const int tid = threadIdx.x;
    const int b0  = blockIdx.x * BROWS;
    const bool isCell = (tid < 256);
    const size_t RS = (size_t)TLEN * VOCABN;

    const int s  = tid & 3;            // k-slice (also batch row for finalize)
    const int up = tid >> 2;           // cell: j-pair 0..63
    const int j0 = 2 * up;
    const int jp = j0 + (j0 >> 5);     // padded u64 index of j0 (j0+1 -> jp+1)
    const int dq = (tid - 256) >> 2;   // dec: v-quad 0..23
    const int v0 = 4 * dq;
    const int sb = 33 * s;             // padded slice base (u64 units)

    // ---------------- per-thread weight registers ----------------
    u64 wd0[32], wd1[32];   // cell: (w,w) for j0, j0+1
    u64 w2a[32], w2b[32];   // dec: (w_v0,w_v1), (w_v2,w_v3)
    u64 bda = 0, bdb = 0;

    if (isCell) {
        const float* r0p = Wcell + j0 * WCS + EMBEDN + s * 32;
        const float* r1p = r0p + WCS;
        #pragma unroll
        for (int k = 0; k < 32; k++) {
            float a = r0p[k], b = r1p[k];
            wd0[k] = pack2(a, a);
            wd1[k] = pack2(b, b);
        }
    } else {
        const float* dp = Wdec + v0 * HID + s * 32;
        #pragma unroll
        for (int k = 0; k < 32; k++) {
            w2a[k] = pack2(dp[k], dp[HID + k]);
            w2b[k] = pack2(dp[2 * HID + k], dp[3 * HID + k]);
        }
        bda = pack2(bdec[v0], bdec[v0 + 1]);
        bdb = pack2(bdec[v0 + 2], bdec[v0 + 3]);
    }

    // ---------------- Et table (threads 0..127) ----------------
    if (tid < HID) {
        const int j = tid;
        float we[EMBEDN];
        #pragma unroll
        for (int k = 0; k < EMBEDN; k++)
            we[k] = Wcell[j * WCS + k];
        const float bc = bcell[j];
        for (int vv = 0; vv < VOCABN; vv++) {
            float a = bc;
            #pragma unroll
            for (int k = 0; k < EMBEDN; k++)
                a = fmaf(emb[vv * EMBEDN + k], we[k], a);
            Et[vv * HID + j] = a;
        }
    }

    // ---------------- token prefetch ----------------
    for (int i = tid; i < BROWS * TLEN; i += NTHR) {
        int t = i >> 2, r = i & 3;
        xs[i] = x[(b0 + r) * TLEN + t];
    }

    // ---------------- initial h into buffer 0 ----------------
    if (isCell) {
        float a = h0[(b0 + s) * HID + j0];
        float b = h0[(b0 + s) * HID + j0 + 1];
        float* hpF = (float*)hpU;
        hpF[(s >> 1) * (2 * KPAD) + jp * 2 + (s & 1)]       = a;
        hpF[(s >> 1) * (2 * KPAD) + (jp + 1) * 2 + (s & 1)] = b;
        hdU[s * KPAD + jp]     = pack2(a, a);
        hdU[s * KPAD + jp + 1] = pack2(b, b);
    }
    __syncthreads();

    float th0 = 0.f, th1 = 0.f;   // cell: last h for (j0,j0+1), row s

    // ---------------- main recurrence ----------------
    #pragma unroll 1
    for (int t = 0; t <= TLEN; t++) {
        if (isCell) {
            if (t < TLEN) {
                const u64* h01 = hpU + (t & 1) * HP_BUF + sb;   // rows (0,1)
                const u64* h23 = h01 + KPAD;                    // rows (2,3)
                u64 aX0 = 0, aY0 = 0, aX1 = 0, aY1 = 0;
                #pragma unroll
                for (int kk = 0; kk < 32; kk++) {
                    u64 hA = h01[kk];
                    u64 hB = h23[kk];
                    aX0 = ffma2(hA, wd0[kk], aX0);
                    aY0 = ffma2(hB, wd0[kk], aY0);
                    aX1 = ffma2(hA, wd1[kk], aX1);
                    aY1 = ffma2(hB, wd1[kk], aY1);
                }
                // reduce 4 k-slices; lane s keeps only what it needs (row s)
                u64 k0 = (s & 2) ? aY0 : aX0;
                u64 g0 = (s & 2) ? aX0 : aY0;
                u64 k1 = (s & 2) ? aY1 : aX1;
                u64 g1 = (s & 2) ? aX1 : aY1;
                k0 = fadd2(k0, shflx64(g0, 2));
                k1 = fadd2(k1, shflx64(g1, 2));
                k0 = fadd2(k0, shflx64(k0, 1));
                k1 = fadd2(k1, shflx64(k1, 1));
                float2 q0 = unpack2(k0), q1 = unpack2(k1);
                float uj0 = (s & 1) ? q0.y : q0.x;
                float uj1 = (s & 1) ? q1.y : q1.x;
                const int xv = xs[t * 4 + s];
                const float2 et2 = *(const float2*)&Et[xv * HID + j0];
                th0 = tanh_fast(uj0 + et2.x);
                th1 = tanh_fast(uj1 + et2.y);
                const int nb = (t + 1) & 1;
                float* hpF = (float*)(hpU + nb * HP_BUF);
                hpF[(s >> 1) * (2 * KPAD) + jp * 2 + (s & 1)]       = th0;
                hpF[(s >> 1) * (2 * KPAD) + (jp + 1) * 2 + (s & 1)] = th1;
                u64* hdp = hdU + nb * HD_BUF + s * KPAD;
                hdp[jp]     = pack2(th0, th0);
                hdp[jp + 1] = pack2(th1, th1);
            }
        } else if (t > 0) {
            // decoder: out[t-1] from h_t (hd buf t&1)
            const u64* hb = hdU + (t & 1) * HD_BUF + sb;
            u64 A0 = 0, A1 = 0, A2 = 0, A3 = 0;
            u64 B0 = 0, B1 = 0, B2 = 0, B3 = 0;
            #pragma unroll
            for (int kk = 0; kk < 32; kk++) {
                u64 d0 = hb[kk];
                u64 d1 = hb[KPAD + kk];
                u64 d2 = hb[2 * KPAD + kk];
                u64 d3 = hb[3 * KPAD + kk];
                A0 = ffma2(d0, w2a[kk], A0);  B0 = ffma2(d0, w2b[kk], B0);
                A1 = ffma2(d1, w2a[kk], A1);  B1 = ffma2(d1, w2b[kk], B1);
                A2 = ffma2(d2, w2a[kk], A2);  B2 = ffma2(d2, w2b[kk], B2);
                A3 = ffma2(d3, w2a[kk], A3);  B3 = ffma2(d3, w2b[kk], B3);
            }
            // reduce-scatter over 4 slices: lane s ends with row-s sums
            u64 kaL = (s & 2) ? A2 : A0;
            u64 kaH = (s & 2) ? A3 : A1;
            u64 gaL = (s & 2) ? A0 : A2;
            u64 gaH = (s & 2) ? A1 : A3;
            kaL = fadd2(kaL, shflx64(gaL, 2));
            kaH = fadd2(kaH, shflx64(gaH, 2));
            u64 ka = (s & 1) ? kaH : kaL;
            u64 ga = (s & 1) ? kaL : kaH;
            ka = fadd2(ka, shflx64(ga, 1));

            u64 kbL = (s & 2) ? B2 : B0;
            u64 kbH = (s & 2) ? B3 : B1;
            u64 gbL = (s & 2) ? B0 : B2;
            u64 gbH = (s & 2) ? B1 : B3;
            kbL = fadd2(kbL, shflx64(gbL, 2));
            kbH = fadd2(kbH, shflx64(gbH, 2));
            u64 kb = (s & 1) ? kbH : kbL;
            u64 gb = (s & 1) ? kbL : kbH;
            kb = fadd2(kb, shflx64(gb, 1));

            ka = fadd2(ka, bda);
            kb = fadd2(kb, bdb);
            float2 ra = unpack2(ka), rb = unpack2(kb);
            float4 o4 = make_float4(ra.x, ra.y, rb.x, rb.y);
            *(float4*)&out[(size_t)(b0 + s) * RS + (size_t)(t - 1) * VOCABN + v0] = o4;
        }
        __syncthreads();
    }

    // ---------------- final hidden state ----------------
    if (isCell && hfin) {
        *(float2*)&hfin[(b0 + s) * HID + j0] = make_float2(th0, th1);
    }
}

extern "C" void kernel_launch(void* const* d_in, const int* in_sizes, int n_in,
                              void* d_out, int out_size)
{
    const int*   x     = (const int*)d_in[0];
    const float* h0    = (const float*)d_in[1];
    const float* emb   = (const float*)d_in[2];
    const float* Wcell = (const float*)d_in[3];
    const float* bcell = (const float*)d_in[4];
    const float* Wdec  = (const float*)d_in[5];
    const float* bdec  = (const float*)d_in[6];

    float* out = (float*)d_out;
    const long long outs_elems = (long long)BATCH * TLEN * VOCABN;
    float* hfin = nullptr;
    if ((long long)out_size >= outs_elems + (long long)BATCH * HID)
        hfin = out + outs_elems;

    cudaFuncSetAttribute(charrnn_kernel,
                         cudaFuncAttributeMaxDynamicSharedMemorySize, SMEM_BYTES);

    charrnn_kernel<<<NBLK, NTHR, SMEM_BYTES>>>(x, h0, emb, Wcell, bcell,
                                               Wdec, bdec, out, hfin);
}

// round 6
// speedup vs baseline: 2.7942x; 1.2106x over previous
#include <cuda_runtime.h>

// CharRNN: B=512, T=2048, VOCAB=96, EMBED=32, HIDDEN=128
// R5: split architecture.
//  Kernel 1 (serial loop, 128 CTAs x 256 thr): cell recurrence only.
//    h_t streamed to a __device__ scratch H[t][b][j] (fp32).
//    Cell layout = R4: thread (j-pair, k-slice s of 4); duplicated (w,w)
//    weights in regs; h row-paired in padded smem; per k: 2 LDS.64 + 4 FFMA2;
//    reduce-scatter shuffles; ex2/rcp tanh; ONE barrier/step.
//  Kernel 2 (GEMM, 16384 CTAs x 256 thr): out = H @ Wdec^T + b, pure fp32,
//    smem-staged tiles (64 rows x 96 cols per CTA), packed FFMA2.

#define VOCABN 96
#define EMBEDN 32
#define HID    128
#define BATCH  512
#define TLEN   2048
#define BROWS  4
#define NBLK   (BATCH / BROWS)   // 128
#define CTHR   256               // cell kernel threads
#define WCS    (EMBEDN + HID)    // 160

#define KPAD   132               // padded u64 per row-pair (k -> k + (k>>5))
#define HP_BUF (2 * KPAD)        // u64 per h buffer (2 row-pairs)
#define ETS    132               // padded Et row stride (floats)

typedef unsigned long long u64;

// 512 MB scratch for all hidden states: H[t][b][j]
__device__ float g_H[(size_t)TLEN * BATCH * HID];

__device__ __forceinline__ u64 ffma2(u64 a, u64 b, u64 c) {
    u64 d;
    asm("fma.rn.f32x2 %0, %1, %2, %3;" : "=l"(d) : "l"(a), "l"(b), "l"(c));
    return d;
}
__device__ __forceinline__ u64 fadd2(u64 a, u64 b) {
    u64 d;
    asm("add.rn.f32x2 %0, %1, %2;" : "=l"(d) : "l"(a), "l"(b));
    return d;
}
__device__ __forceinline__ u64 pack2(float x, float y) {
    u64 d;
    asm("mov.b64 %0, {%1, %2};" : "=l"(d) : "f"(x), "f"(y));
    return d;
}
__device__ __forceinline__ float2 unpack2(u64 a) {
    float2 r;
    asm("mov.b64 {%0, %1}, %2;" : "=f"(r.x), "=f"(r.y) : "l"(a));
    return r;
}
__device__ __forceinline__ u64 shflx64(u64 v, int m) {
    float2 p = unpack2(v);
    p.x = __shfl_xor_sync(0xffffffffu, p.x, m);
    p.y = __shfl_xor_sync(0xffffffffu, p.y, m);
    return pack2(p.x, p.y);
}
__device__ __forceinline__ float tanh_fast(float x) {
    float e;
    asm("ex2.approx.f32 %0, %1;" : "=f"(e) : "f"(x * 2.8853900817779268f));
    float r;
    asm("rcp.approx.f32 %0, %1;" : "=f"(r) : "f"(e + 1.0f));
    return fmaf(-2.0f, r, 1.0f);
}

// ---------------- cell-loop kernel smem ----------------
//  Et : 96*132 floats (padded)
//  hp : 2 buf * HP_BUF u64
//  xs : 2048*4 ints
#define F_ET 0
#define F_HP (F_ET + VOCABN*ETS)                 // 12672 floats
#define F_XS (F_HP + 2*HP_BUF*2)                 // + 1056
#define C_SMEM_FLOATS (F_XS + BROWS*TLEN)
#define C_SMEM_BYTES  (C_SMEM_FLOATS * 4)

__global__ void __launch_bounds__(CTHR, 1)
charrnn_cell_kernel(const int* __restrict__ x,
                    const float* __restrict__ h0,
                    const float* __restrict__ emb,
                    const float* __restrict__ Wcell,   // [128][160]
                    const float* __restrict__ bcell,   // [128]
                    float* __restrict__ hfin)          // [512][128] or null
{
    extern __shared__ float smem[];
    float* Et  = smem + F_ET;
    u64*   hpU = (u64*)(smem + F_HP);
    int*   xs  = (int*)(smem + F_XS);

    const int tid = threadIdx.x;
    const int b0  = blockIdx.x * BROWS;

    const int s  = tid & 3;            // k-slice; also finalize batch row
    const int up = tid >> 2;           // j-pair 0..63
    const int j0 = 2 * up;
    const int jp = j0 + (j0 >> 5);     // padded u64 index of j0
    const int sb = 33 * s;             // padded slice base (u64)

    // duplicated (w,w) weights for j0, j0+1 over this k-slice
    u64 wd0[32], wd1[32];
    {
        const float* r0p = Wcell + j0 * WCS + EMBEDN + s * 32;
        const float* r1p = r0p + WCS;
        #pragma unroll
        for (int k = 0; k < 32; k++) {
            float a = r0p[k], b = r1p[k];
            wd0[k] = pack2(a, a);
            wd1[k] = pack2(b, b);
        }
    }

    // Et table (threads 0..127): Et[v*ETS + j] = b_cell[j] + emb[v] . We[j]
    if (tid < HID) {
        const int j = tid;
        float we[EMBEDN];
        #pragma unroll
        for (int k = 0; k < EMBEDN; k++)
            we[k] = Wcell[j * WCS + k];
        const float bc = bcell[j];
        for (int vv = 0; vv < VOCABN; vv++) {
            float a = bc;
            #pragma unroll
            for (int k = 0; k < EMBEDN; k++)
                a = fmaf(emb[vv * EMBEDN + k], we[k], a);
            Et[vv * ETS + j] = a;
        }
    }

    // token prefetch: xs[t*4 + r] = x[(b0+r)*T + t]
    for (int i = tid; i < BROWS * TLEN; i += CTHR) {
        int t = i >> 2, r = i & 3;
        xs[i] = x[(b0 + r) * TLEN + t];
    }

    // initial h into buffer 0 (row-paired padded layout)
    {
        float a = h0[(b0 + s) * HID + j0];
        float b = h0[(b0 + s) * HID + j0 + 1];
        float* hpF = (float*)hpU;
        hpF[(s >> 1) * (2 * KPAD) + jp * 2 + (s & 1)]       = a;
        hpF[(s >> 1) * (2 * KPAD) + (jp + 1) * 2 + (s & 1)] = b;
    }
    __syncthreads();

    float th0 = 0.f, th1 = 0.f;

    #pragma unroll 1
    for (int t = 0; t < TLEN; t++) {
        const u64* h01 = hpU + (t & 1) * HP_BUF + sb;   // rows (0,1), my slice
        const u64* h23 = h01 + KPAD;                    // rows (2,3)
        u64 aX0 = 0, aY0 = 0, aX1 = 0, aY1 = 0;
        #pragma unroll
        for (int kk = 0; kk < 32; kk++) {
            u64 hA = h01[kk];
            u64 hB = h23[kk];
            aX0 = ffma2(hA, wd0[kk], aX0);
            aY0 = ffma2(hB, wd0[kk], aY0);
            aX1 = ffma2(hA, wd1[kk], aX1);
            aY1 = ffma2(hB, wd1[kk], aY1);
        }
        // reduce-scatter over 4 k-slices; lane s keeps batch row s
        u64 k0 = (s & 2) ? aY0 : aX0;
        u64 g0 = (s & 2) ? aX0 : aY0;
        u64 k1 = (s & 2) ? aY1 : aX1;
        u64 g1 = (s & 2) ? aX1 : aY1;
        k0 = fadd2(k0, shflx64(g0, 2));
        k1 = fadd2(k1, shflx64(g1, 2));
        k0 = fadd2(k0, shflx64(k0, 1));
        k1 = fadd2(k1, shflx64(k1, 1));
        float2 q0 = unpack2(k0), q1 = unpack2(k1);
        float uj0 = (s & 1) ? q0.y : q0.x;
        float uj1 = (s & 1) ? q1.y : q1.x;
        const int xv = xs[t * 4 + s];
        const float2 et2 = *(const float2*)&Et[xv * ETS + j0];
        th0 = tanh_fast(uj0 + et2.x);
        th1 = tanh_fast(uj1 + et2.y);
        // store h_t: smem (next buffer) + gmem scratch for decoder
        const int nb = (t + 1) & 1;
        float* hpF = (float*)(hpU + nb * HP_BUF);
        hpF[(s >> 1) * (2 * KPAD) + jp * 2 + (s & 1)]       = th0;
        hpF[(s >> 1) * (2 * KPAD) + (jp + 1) * 2 + (s & 1)] = th1;
        *(float2*)&g_H[((size_t)t * BATCH + (b0 + s)) * HID + j0] =
            make_float2(th0, th1);
        __syncthreads();
    }

    if (hfin)
        *(float2*)&hfin[(b0 + s) * HID + j0] = make_float2(th0, th1);
}

// ---------------- decoder GEMM kernel ----------------
// out[b][t][v] = H[t][b][:] . Wdec[v][:] + bdec[v]
// CTA: 64 rows x 96 v; 256 thr = 64 r x 4 vgroups (24 v each).
#define G_ROWS 64
#define G_THR  256
#define WT_S   100                          // padded W^T row stride (16B-align ok)
#define HT_S   132                          // padded h-tile row stride
#define G_WT   0                            // wt[128][WT_S]
#define G_HT   (G_WT + 128*WT_S)            // ht[64][HT_S]
#define G_BD   (G_HT + G_ROWS*HT_S)         // bd[96]
#define G_SMEM_FLOATS (G_BD + 96)
#define G_SMEM_BYTES  (G_SMEM_FLOATS * 4)

__global__ void __launch_bounds__(G_THR, 2)
charrnn_dec_kernel(const float* __restrict__ Wdec,   // [96][128]
                   const float* __restrict__ bdec,   // [96]
                   float* __restrict__ out)          // [512][2048][96]
{
    extern __shared__ float smem[];
    float* wt = smem + G_WT;
    float* ht = smem + G_HT;
    float* bd = smem + G_BD;

    const int tid  = threadIdx.x;
    const size_t row0 = (size_t)blockIdx.x * G_ROWS;

    // stage W^T (coalesced LDG, strided STS: 4-way conflicts, one-time)
    for (int i = tid; i < VOCABN * HID; i += G_THR) {
        int v = i >> 7, k = i & 127;
        wt[k * WT_S + v] = Wdec[i];
    }
    if (tid < VOCABN) bd[tid] = bdec[tid];

    // stage h tile (coalesced)
    for (int i = tid; i < G_ROWS * HID; i += G_THR) {
        int r = i >> 7, k = i & 127;
        ht[r * HT_S + k] = g_H[(row0 + r) * HID + k];
    }
    __syncthreads();

    const int r  = tid >> 2;         // row within tile
    const int vg = tid & 3;          // v group
    const int v0 = vg * 24;

    u64 acc[12];
    #pragma unroll
    for (int i = 0; i < 12; i++) acc[i] = 0ull;

    const float* hrow = ht + r * HT_S;
    const float* wk   = wt + v0;
    #pragma unroll 4
    for (int k = 0; k < HID; k++) {
        float hk = hrow[k];
        u64 h2 = pack2(hk, hk);
        const float4* wp = (const float4*)(wk + k * WT_S);
        #pragma unroll
        for (int q = 0; q < 6; q++) {
            float4 w4 = wp[q];
            acc[2 * q]     = ffma2(h2, pack2(w4.x, w4.y), acc[2 * q]);
            acc[2 * q + 1] = ffma2(h2, pack2(w4.z, w4.w), acc[2 * q + 1]);
        }
    }

    // epilogue: add bias, store
    const size_t rr = row0 + r;          // = t*512 + b
    const size_t tt = rr >> 9;
    const size_t bb = rr & 511;
    float* op = out + (bb * TLEN + tt) * VOCABN + v0;
    #pragma unroll
    for (int q = 0; q < 6; q++) {
        float2 lo = unpack2(acc[2 * q]);
        float2 hi = unpack2(acc[2 * q + 1]);
        float4 o4;
        o4.x = lo.x + bd[v0 + 4 * q + 0];
        o4.y = lo.y + bd[v0 + 4 * q + 1];
        o4.z = hi.x + bd[v0 + 4 * q + 2];
        o4.w = hi.y + bd[v0 + 4 * q + 3];
        *(float4*)(op + 4 * q) = o4;
    }
}

extern "C" void kernel_launch(void* const* d_in, const int* in_sizes, int n_in,
                              void* d_out, int out_size)
{
    const int*   x     = (const int*)d_in[0];
    const float* h0    = (const float*)d_in[1];
    const float* emb   = (const float*)d_in[2];
    const float* Wcell = (const float*)d_in[3];
    const float* bcell = (const float*)d_in[4];
    const float* Wdec  = (const float*)d_in[5];
    const float* bdec  = (const float*)d_in[6];

    float* out = (float*)d_out;
    const long long outs_elems = (long long)BATCH * TLEN * VOCABN;
    float* hfin = nullptr;
    if ((long long)out_size >= outs_elems + (long long)BATCH * HID)
        hfin = out + outs_elems;

    cudaFuncSetAttribute(charrnn_cell_kernel,
                         cudaFuncAttributeMaxDynamicSharedMemorySize, C_SMEM_BYTES);
    cudaFuncSetAttribute(charrnn_dec_kernel,
                         cudaFuncAttributeMaxDynamicSharedMemorySize, G_SMEM_BYTES);

    charrnn_cell_kernel<<<NBLK, CTHR, C_SMEM_BYTES>>>(x, h0, emb, Wcell, bcell,
                                                      hfin);

    const int gblocks = (int)(((size_t)TLEN * BATCH) / G_ROWS);   // 16384
    charrnn_dec_kernel<<<gblocks, G_THR, G_SMEM_BYTES>>>(Wdec, bdec, out);
}